// round 16
// baseline (speedup 1.0000x reference)
#include <cuda_runtime.h>
#include <cuda_bf16.h>
#include <cuda_fp16.h>

#define NN 50000
#define EE 800000

// Scratch (no cudaMalloc allowed)
__device__ __half g_hth[NN * 128]; // h @ W_node, fp16, [N][H*F] (12.8MB)
__device__ float g_ss[NN * 8];     // per-node src attention scalar
__device__ float g_sd[NN * 8];     // per-node dst attention scalar
__device__ float g_se[NN * 8];     // sum of exp per (dst, head)
__device__ float g_exp[EE * 8];    // per-(edge,head) exp(leaky_relu(logit))
__device__ uint4 g_Bhi[2048];      // W^T hi bf16, [n=128][k=128] (32KB)
__device__ uint4 g_Blo[2048];      // W^T lo bf16

// ---------------- helpers ----------------
__device__ __forceinline__ void red_add_v4(float* p, float4 v) {
    asm volatile("red.global.add.v4.f32 [%0], {%1,%2,%3,%4};"
                 :: "l"(p), "f"(v.x), "f"(v.y), "f"(v.z), "f"(v.w) : "memory");
}
__device__ __forceinline__ unsigned smem_u32(const void* p) {
    unsigned a;
    asm("{ .reg .u64 t; cvta.to.shared.u64 t, %1; cvt.u32.u64 %0, t; }"
        : "=r"(a) : "l"(p));
    return a;
}
__device__ __forceinline__ void ldsm4(unsigned* r, unsigned addr) {
    asm volatile("ldmatrix.sync.aligned.m8n8.x4.shared.b16 {%0,%1,%2,%3}, [%4];"
                 : "=r"(r[0]), "=r"(r[1]), "=r"(r[2]), "=r"(r[3]) : "r"(addr));
}
__device__ __forceinline__ void mma_bf16(float* d, const unsigned* a,
                                         unsigned b0, unsigned b1) {
    asm volatile(
        "mma.sync.aligned.m16n8k16.row.col.f32.bf16.bf16.f32 "
        "{%0,%1,%2,%3}, {%4,%5,%6,%7}, {%8,%9}, {%0,%1,%2,%3};"
        : "+f"(d[0]), "+f"(d[1]), "+f"(d[2]), "+f"(d[3])
        : "r"(a[0]), "r"(a[1]), "r"(a[2]), "r"(a[3]), "r"(b0), "r"(b1));
}
__device__ __forceinline__ int swz(int c, int r) {
    return (c & 8) | ((c ^ r) & 7);
}

// ---------------------------------------------------------------------------
// K0: prepack W^T hi/lo bf16 (B[n][k] = W[k][n]).
// ---------------------------------------------------------------------------
__global__ void k_prepW(const float* __restrict__ Wn) {
    int idx = blockIdx.x * 256 + threadIdx.x;
    if (idx >= 128 * 128) return;
    int n = idx >> 7, k = idx & 127;
    float v = Wn[k * 128 + n];
    __nv_bfloat16 hi = __float2bfloat16(v);
    __nv_bfloat16 lo = __float2bfloat16(v - __bfloat162float(hi));
    ((__nv_bfloat16*)g_Bhi)[n * 128 + k] = hi;
    ((__nv_bfloat16*)g_Blo)[n * 128 + k] = lo;
}

// ---------------------------------------------------------------------------
// K1: bf16 3-term GEMM via mma.sync (D = Ahi*Bhi + Ahi*Blo + Alo*Bhi).
// Epilogue: fp16 g_hth store + fused s_src/s_dst scalars (fp32 accumulators).
// CTA tile: 64 nodes x 128 cols; 8 warps = (row quarter rh, col half ch).
// ---------------------------------------------------------------------------
#define SM_AHI 0
#define SM_ALO 16384
#define SM_BHI 32768
#define SM_BLO 65536
#define SM_TOT 98304

__global__ __launch_bounds__(256, 2) void k_gemm(const float* __restrict__ hin,
                                                 const float* __restrict__ asrc,
                                                 const float* __restrict__ adst) {
    extern __shared__ char sm[];
    const unsigned sb = smem_u32(sm);
    const int tid = threadIdx.x, wid = tid >> 5, lid = tid & 31;
    const int n0 = blockIdx.x << 6;

    // B tiles (swizzled 16B-chunk copy)
#pragma unroll
    for (int i = 0; i < 8; i++) {
        int idx = tid + i * 256;
        int r = idx >> 4, c = idx & 15;
        int off = r * 256 + swz(c, r & 7) * 16;
        *(uint4*)(sm + SM_BHI + off) = g_Bhi[idx];
        *(uint4*)(sm + SM_BLO + off) = g_Blo[idx];
    }
    // A tiles: fp32 -> hi/lo bf16, swizzled
    const float4* h4 = (const float4*)hin;
#pragma unroll
    for (int i = 0; i < 8; i++) {
        int idx = tid + i * 256;
        int r = idx >> 5, c4 = idx & 31;
        int k = c4 << 2;
        float4 v = make_float4(0.f, 0.f, 0.f, 0.f);
        if (n0 + r < NN) v = h4[(size_t)(n0 + r) * 32 + c4];
        __nv_bfloat162 hA = __floats2bfloat162_rn(v.x, v.y);
        __nv_bfloat162 hB = __floats2bfloat162_rn(v.z, v.w);
        __nv_bfloat162 lA = __floats2bfloat162_rn(v.x - __bfloat162float(hA.x),
                                                  v.y - __bfloat162float(hA.y));
        __nv_bfloat162 lB = __floats2bfloat162_rn(v.z - __bfloat162float(hB.x),
                                                  v.w - __bfloat162float(hB.y));
        int off = r * 256 + swz(k >> 3, r & 7) * 16 + (k & 7) * 2;
        *(uint2*)(sm + SM_AHI + off) = make_uint2(*(unsigned*)&hA, *(unsigned*)&hB);
        *(uint2*)(sm + SM_ALO + off) = make_uint2(*(unsigned*)&lA, *(unsigned*)&lB);
    }
    __syncthreads();

    const int rh = wid & 3;
    const int ch = wid >> 2;

    float acc[8][4];
#pragma unroll
    for (int t = 0; t < 8; t++)
#pragma unroll
        for (int j = 0; j < 4; j++) acc[t][j] = 0.f;

    const int arow = rh * 16 + (lid & 15);
    const int bl = (lid & 7) + ((lid >> 4) << 3);
    const int bko = (lid >> 3) & 1;

#pragma unroll
    for (int ks = 0; ks < 8; ks++) {
        unsigned ahi[4], alo[4];
        {
            int c = ks * 2 + (lid >> 4);
            int aoff = arow * 256 + swz(c, arow & 7) * 16;
            ldsm4(ahi, sb + SM_AHI + aoff);
            ldsm4(alo, sb + SM_ALO + aoff);
        }
#pragma unroll
        for (int p = 0; p < 4; p++) {
            int n = ch * 64 + p * 16 + bl;
            int c = ks * 2 + bko;
            int boff = n * 256 + swz(c, n & 7) * 16;
            unsigned bhi[4], blo[4];
            ldsm4(bhi, sb + SM_BHI + boff);
            ldsm4(blo, sb + SM_BLO + boff);
            mma_bf16(acc[2 * p],     ahi, bhi[0], bhi[1]);
            mma_bf16(acc[2 * p],     ahi, blo[0], blo[1]);
            mma_bf16(acc[2 * p],     alo, bhi[0], bhi[1]);
            mma_bf16(acc[2 * p + 1], ahi, bhi[2], bhi[3]);
            mma_bf16(acc[2 * p + 1], ahi, blo[2], blo[3]);
            mma_bf16(acc[2 * p + 1], alo, bhi[2], bhi[3]);
        }
    }

    // --- epilogue: fp16 g_hth store + fused attention scalars ---
    const int r0 = n0 + rh * 16 + (lid >> 2);
    const int r1 = r0 + 8;
#pragma unroll
    for (int t = 0; t < 8; t++) {
        int gcol = ch * 64 + t * 8 + 2 * (lid & 3);
        if (r0 < NN) *(__half2*)(g_hth + (size_t)r0 * 128 + gcol) =
            __floats2half2_rn(acc[t][0], acc[t][1]);
        if (r1 < NN) *(__half2*)(g_hth + (size_t)r1 * 128 + gcol) =
            __floats2half2_rn(acc[t][2], acc[t][3]);
    }
    // heads owned by this warp: ch*4+u (u=0..3); head u uses t = 2u, 2u+1
    const int q2 = 2 * (lid & 3);
#pragma unroll
    for (int u = 0; u < 4; u++) {
        int hh = ch * 4 + u;
        const float* as = asrc + hh * 16;
        const float* ad = adst + hh * 16;
        float a0 = __ldg(as + q2),     a1 = __ldg(as + q2 + 1);
        float a2 = __ldg(as + 8 + q2), a3 = __ldg(as + 8 + q2 + 1);
        float b0 = __ldg(ad + q2),     b1 = __ldg(ad + q2 + 1);
        float b2 = __ldg(ad + 8 + q2), b3 = __ldg(ad + 8 + q2 + 1);
        float s0 = acc[2*u][0]*a0 + acc[2*u][1]*a1 + acc[2*u+1][0]*a2 + acc[2*u+1][1]*a3;
        float s1 = acc[2*u][2]*a0 + acc[2*u][3]*a1 + acc[2*u+1][2]*a2 + acc[2*u+1][3]*a3;
        float d0 = acc[2*u][0]*b0 + acc[2*u][1]*b1 + acc[2*u+1][0]*b2 + acc[2*u+1][1]*b3;
        float d1 = acc[2*u][2]*b0 + acc[2*u][3]*b1 + acc[2*u+1][2]*b2 + acc[2*u+1][3]*b3;
        s0 += __shfl_xor_sync(0xffffffffu, s0, 1);
        s0 += __shfl_xor_sync(0xffffffffu, s0, 2);
        s1 += __shfl_xor_sync(0xffffffffu, s1, 1);
        s1 += __shfl_xor_sync(0xffffffffu, s1, 2);
        d0 += __shfl_xor_sync(0xffffffffu, d0, 1);
        d0 += __shfl_xor_sync(0xffffffffu, d0, 2);
        d1 += __shfl_xor_sync(0xffffffffu, d1, 1);
        d1 += __shfl_xor_sync(0xffffffffu, d1, 2);
        if ((lid & 3) == 0) {
            if (r0 < NN) { g_ss[r0 * 8 + hh] = s0; g_sd[r0 * 8 + hh] = d0; }
            if (r1 < NN) { g_ss[r1 * 8 + hh] = s1; g_sd[r1 * 8 + hh] = d1; }
        }
    }
}

// ---------------------------------------------------------------------------
// K3: edge pass A — compute exp(leaky_relu(logit)), SPILL to g_exp
// (coalesced st.v4), and accumulate sum per (dst, head) via red.v4.
// 2 threads/edge (4 heads each).
// ---------------------------------------------------------------------------
__global__ void k_edgeA(const int* __restrict__ ei,
                        const float* __restrict__ ef,
                        const float* __restrict__ We) {
    int gid = blockIdx.x * 256 + threadIdx.x;   // grid exact: (EE*2) % 256 == 0
    int e = gid >> 1;
    int half = gid & 1;
    int src = ei[e];
    int dst = ei[EE + e];
    float f = __ldg(ef + e);
    float4 s = ((const float4*)g_ss)[src * 2 + half];
    float4 d = ((const float4*)g_sd)[dst * 2 + half];
    float4 w = ((const float4*)We)[half];
    float4 x;
    x.x = s.x + d.x + f * w.x;
    x.y = s.y + d.y + f * w.y;
    x.z = s.z + d.z + f * w.z;
    x.w = s.w + d.w + f * w.w;
    x.x = __expf(fmaxf(x.x, 0.2f * x.x));
    x.y = __expf(fmaxf(x.y, 0.2f * x.y));
    x.z = __expf(fmaxf(x.z, 0.2f * x.z));
    x.w = __expf(fmaxf(x.w, 0.2f * x.w));
    *(float4*)(g_exp + (size_t)e * 8 + half * 4) = x;   // coalesced spill
    red_add_v4(g_se + dst * 8 + half * 4, x);
}

// ---------------------------------------------------------------------------
// K4: edge pass B — alpha = 0.125 * exp (coalesced) / se (gather); fp16 row
// gather + HALF2 weighting/reduction; fp32 only at the final atomic.
// 8 lanes/edge; lane l loads chunks l and 8+l (head l>>1 / 4+(l>>1),
// feat-half l&1). xor-2 + xor-4 HADD2 reduction leaves lanes 0/1 holding
// feats 0-7 / 8-15 summed over all heads.
// ---------------------------------------------------------------------------
__global__ void k_edgeB(const int* __restrict__ ei,
                        float* __restrict__ out) {
    int gid = blockIdx.x * 256 + threadIdx.x;  // grid exact: (EE*8) % 256 == 0
    int e = gid >> 3;
    int l = gid & 7;
    int src = ei[e];
    int dst = ei[EE + e];

    // independent gathers issued early
    float expv = __ldg(g_exp + (size_t)e * 8 + l);   // fully coalesced
    float sev = g_se[dst * 8 + l];                   // gathered sum
    const uint4* hv = (const uint4*)(g_hth + (size_t)src * 128);
    uint4 ua = hv[l];        // head l>>1,      feat-half l&1
    uint4 ub = hv[8 + l];    // head 4+(l>>1),  feat-half l&1

    float alpha = 0.125f * expv / sev;   // this lane = head l (rcp+mul, fast-math)

    float a0 = __shfl_sync(0xffffffffu, alpha, (l >> 1), 8);
    float a1 = __shfl_sync(0xffffffffu, alpha, 4 + (l >> 1), 8);
    __half2 a0h = __float2half2_rn(a0);
    __half2 a1h = __float2half2_rn(a1);

    const __half2* uah = (const __half2*)&ua;
    const __half2* ubh = (const __half2*)&ub;
    unsigned acc[4];
#pragma unroll
    for (int i = 0; i < 4; i++) {
        __half2 t = __hfma2(uah[i], a0h, __hmul2(ubh[i], a1h));
        acc[i] = *(unsigned*)&t;
    }
    // head reduction (parity == feat-half preserved)
#pragma unroll
    for (int i = 0; i < 4; i++) {
        unsigned o = __shfl_xor_sync(0xffffffffu, acc[i], 2, 8);
        __half2 t = __hadd2(*(__half2*)&acc[i], *(__half2*)&o);
        acc[i] = *(unsigned*)&t;
    }
#pragma unroll
    for (int i = 0; i < 4; i++) {
        unsigned o = __shfl_xor_sync(0xffffffffu, acc[i], 4, 8);
        __half2 t = __hadd2(*(__half2*)&acc[i], *(__half2*)&o);
        acc[i] = *(unsigned*)&t;
    }

    if (l < 2) {
        float2 f0 = __half22float2(*(__half2*)&acc[0]);
        float2 f1 = __half22float2(*(__half2*)&acc[1]);
        float2 f2 = __half22float2(*(__half2*)&acc[2]);
        float2 f3 = __half22float2(*(__half2*)&acc[3]);
        float* base = out + (size_t)dst * 16 + l * 8;
        red_add_v4(base,     make_float4(f0.x, f0.y, f1.x, f1.y));
        red_add_v4(base + 4, make_float4(f2.x, f2.y, f3.x, f3.y));
    }
}

// ---------------------------------------------------------------------------
extern "C" void kernel_launch(void* const* d_in, const int* in_sizes, int n_in,
                              void* d_out, int out_size) {
    const float* h    = (const float*)d_in[0];
    const int*   ei   = (const int*)d_in[1];
    const float* ef   = (const float*)d_in[2];
    const float* Wn   = (const float*)d_in[3];
    const float* We   = (const float*)d_in[4];
    const float* asrc = (const float*)d_in[5];
    const float* adst = (const float*)d_in[6];
    float* out = (float*)d_out;

    cudaFuncSetAttribute(k_gemm, cudaFuncAttributeMaxDynamicSharedMemorySize, SM_TOT);

    void* p = nullptr;
    cudaGetSymbolAddress(&p, g_se);
    cudaMemsetAsync(p, 0, (size_t)NN * 8 * sizeof(float));
    cudaMemsetAsync(out, 0, (size_t)NN * 16 * sizeof(float));

    k_prepW<<<64, 256>>>(Wn);
    k_gemm<<<(NN + 63) / 64, 256, SM_TOT>>>(h, asrc, adst);
    k_edgeA<<<(EE * 2) / 256, 256>>>(ei, ef, We);
    k_edgeB<<<(EE * 8) / 256, 256>>>(ei, out);
}

// round 17
// speedup vs baseline: 1.0813x; 1.0813x over previous
#include <cuda_runtime.h>
#include <cuda_bf16.h>
#include <cuda_fp16.h>

#define NN 50000
#define EE 800000

// Scratch (no cudaMalloc allowed)
__device__ __half g_hth[NN * 128]; // h @ W_node, fp16, [N][H*F] (12.8MB)
__device__ float g_ss[NN * 8];     // per-node src attention scalar
__device__ float g_sd[NN * 8];     // per-node dst attention scalar
__device__ float g_se[NN * 8];     // sum of exp per (dst, head)
__device__ __half g_exph[EE * 8];  // per-(edge,head) exp, fp16 (12.8MB)
__device__ uint4 g_Bhi[2048];      // W^T hi bf16, [n=128][k=128] (32KB)
__device__ uint4 g_Blo[2048];      // W^T lo bf16

// ---------------- helpers ----------------
__device__ __forceinline__ void red_add_v4(float* p, float4 v) {
    asm volatile("red.global.add.v4.f32 [%0], {%1,%2,%3,%4};"
                 :: "l"(p), "f"(v.x), "f"(v.y), "f"(v.z), "f"(v.w) : "memory");
}
__device__ __forceinline__ unsigned smem_u32(const void* p) {
    unsigned a;
    asm("{ .reg .u64 t; cvta.to.shared.u64 t, %1; cvt.u32.u64 %0, t; }"
        : "=r"(a) : "l"(p));
    return a;
}
__device__ __forceinline__ void ldsm4(unsigned* r, unsigned addr) {
    asm volatile("ldmatrix.sync.aligned.m8n8.x4.shared.b16 {%0,%1,%2,%3}, [%4];"
                 : "=r"(r[0]), "=r"(r[1]), "=r"(r[2]), "=r"(r[3]) : "r"(addr));
}
__device__ __forceinline__ void mma_bf16(float* d, const unsigned* a,
                                         unsigned b0, unsigned b1) {
    asm volatile(
        "mma.sync.aligned.m16n8k16.row.col.f32.bf16.bf16.f32 "
        "{%0,%1,%2,%3}, {%4,%5,%6,%7}, {%8,%9}, {%0,%1,%2,%3};"
        : "+f"(d[0]), "+f"(d[1]), "+f"(d[2]), "+f"(d[3])
        : "r"(a[0]), "r"(a[1]), "r"(a[2]), "r"(a[3]), "r"(b0), "r"(b1));
}
__device__ __forceinline__ int swz(int c, int r) {
    return (c & 8) | ((c ^ r) & 7);
}

// ---------------------------------------------------------------------------
// K0: prepack W^T hi/lo bf16 (B[n][k] = W[k][n]) + zero g_se and out.
// Grid: 200 blocks x 256 = 51200 threads.
// ---------------------------------------------------------------------------
__global__ void k_prep(const float* __restrict__ Wn, float* __restrict__ out) {
    int idx = blockIdx.x * 256 + threadIdx.x;
    if (idx < 128 * 128) {
        int n = idx >> 7, k = idx & 127;
        float v = Wn[k * 128 + n];
        __nv_bfloat16 hi = __float2bfloat16(v);
        __nv_bfloat16 lo = __float2bfloat16(v - __bfloat162float(hi));
        ((__nv_bfloat16*)g_Bhi)[n * 128 + k] = hi;
        ((__nv_bfloat16*)g_Blo)[n * 128 + k] = lo;
    }
    // zero g_se: 400000 floats = 100000 float4
    float4 z = make_float4(0.f, 0.f, 0.f, 0.f);
    for (int i = idx; i < 100000; i += 51200)
        ((float4*)g_se)[i] = z;
    // zero out: 800000 floats = 200000 float4
    for (int i = idx; i < 200000; i += 51200)
        ((float4*)out)[i] = z;
}

// ---------------------------------------------------------------------------
// K1: bf16 3-term GEMM via mma.sync (D = Ahi*Bhi + Ahi*Blo + Alo*Bhi).
// Epilogue: fp16 g_hth store + fused s_src/s_dst scalars (fp32 accumulators).
// CTA tile: 64 nodes x 128 cols; 8 warps = (row quarter rh, col half ch).
// ---------------------------------------------------------------------------
#define SM_AHI 0
#define SM_ALO 16384
#define SM_BHI 32768
#define SM_BLO 65536
#define SM_TOT 98304

__global__ __launch_bounds__(256, 2) void k_gemm(const float* __restrict__ hin,
                                                 const float* __restrict__ asrc,
                                                 const float* __restrict__ adst) {
    extern __shared__ char sm[];
    const unsigned sb = smem_u32(sm);
    const int tid = threadIdx.x, wid = tid >> 5, lid = tid & 31;
    const int n0 = blockIdx.x << 6;

    // B tiles (swizzled 16B-chunk copy)
#pragma unroll
    for (int i = 0; i < 8; i++) {
        int idx = tid + i * 256;
        int r = idx >> 4, c = idx & 15;
        int off = r * 256 + swz(c, r & 7) * 16;
        *(uint4*)(sm + SM_BHI + off) = g_Bhi[idx];
        *(uint4*)(sm + SM_BLO + off) = g_Blo[idx];
    }
    // A tiles: fp32 -> hi/lo bf16, swizzled
    const float4* h4 = (const float4*)hin;
#pragma unroll
    for (int i = 0; i < 8; i++) {
        int idx = tid + i * 256;
        int r = idx >> 5, c4 = idx & 31;
        int k = c4 << 2;
        float4 v = make_float4(0.f, 0.f, 0.f, 0.f);
        if (n0 + r < NN) v = h4[(size_t)(n0 + r) * 32 + c4];
        __nv_bfloat162 hA = __floats2bfloat162_rn(v.x, v.y);
        __nv_bfloat162 hB = __floats2bfloat162_rn(v.z, v.w);
        __nv_bfloat162 lA = __floats2bfloat162_rn(v.x - __bfloat162float(hA.x),
                                                  v.y - __bfloat162float(hA.y));
        __nv_bfloat162 lB = __floats2bfloat162_rn(v.z - __bfloat162float(hB.x),
                                                  v.w - __bfloat162float(hB.y));
        int off = r * 256 + swz(k >> 3, r & 7) * 16 + (k & 7) * 2;
        *(uint2*)(sm + SM_AHI + off) = make_uint2(*(unsigned*)&hA, *(unsigned*)&hB);
        *(uint2*)(sm + SM_ALO + off) = make_uint2(*(unsigned*)&lA, *(unsigned*)&lB);
    }
    __syncthreads();

    const int rh = wid & 3;
    const int ch = wid >> 2;

    float acc[8][4];
#pragma unroll
    for (int t = 0; t < 8; t++)
#pragma unroll
        for (int j = 0; j < 4; j++) acc[t][j] = 0.f;

    const int arow = rh * 16 + (lid & 15);
    const int bl = (lid & 7) + ((lid >> 4) << 3);
    const int bko = (lid >> 3) & 1;

#pragma unroll
    for (int ks = 0; ks < 8; ks++) {
        unsigned ahi[4], alo[4];
        {
            int c = ks * 2 + (lid >> 4);
            int aoff = arow * 256 + swz(c, arow & 7) * 16;
            ldsm4(ahi, sb + SM_AHI + aoff);
            ldsm4(alo, sb + SM_ALO + aoff);
        }
#pragma unroll
        for (int p = 0; p < 4; p++) {
            int n = ch * 64 + p * 16 + bl;
            int c = ks * 2 + bko;
            int boff = n * 256 + swz(c, n & 7) * 16;
            unsigned bhi[4], blo[4];
            ldsm4(bhi, sb + SM_BHI + boff);
            ldsm4(blo, sb + SM_BLO + boff);
            mma_bf16(acc[2 * p],     ahi, bhi[0], bhi[1]);
            mma_bf16(acc[2 * p],     ahi, blo[0], blo[1]);
            mma_bf16(acc[2 * p],     alo, bhi[0], bhi[1]);
            mma_bf16(acc[2 * p + 1], ahi, bhi[2], bhi[3]);
            mma_bf16(acc[2 * p + 1], ahi, blo[2], blo[3]);
            mma_bf16(acc[2 * p + 1], alo, bhi[2], bhi[3]);
        }
    }

    // --- epilogue: fp16 g_hth store + fused attention scalars ---
    const int r0 = n0 + rh * 16 + (lid >> 2);
    const int r1 = r0 + 8;
#pragma unroll
    for (int t = 0; t < 8; t++) {
        int gcol = ch * 64 + t * 8 + 2 * (lid & 3);
        if (r0 < NN) *(__half2*)(g_hth + (size_t)r0 * 128 + gcol) =
            __floats2half2_rn(acc[t][0], acc[t][1]);
        if (r1 < NN) *(__half2*)(g_hth + (size_t)r1 * 128 + gcol) =
            __floats2half2_rn(acc[t][2], acc[t][3]);
    }
    // heads owned by this warp: ch*4+u (u=0..3); head u uses t = 2u, 2u+1
    const int q2 = 2 * (lid & 3);
#pragma unroll
    for (int u = 0; u < 4; u++) {
        int hh = ch * 4 + u;
        const float* as = asrc + hh * 16;
        const float* ad = adst + hh * 16;
        float a0 = __ldg(as + q2),     a1 = __ldg(as + q2 + 1);
        float a2 = __ldg(as + 8 + q2), a3 = __ldg(as + 8 + q2 + 1);
        float b0 = __ldg(ad + q2),     b1 = __ldg(ad + q2 + 1);
        float b2 = __ldg(ad + 8 + q2), b3 = __ldg(ad + 8 + q2 + 1);
        float s0 = acc[2*u][0]*a0 + acc[2*u][1]*a1 + acc[2*u+1][0]*a2 + acc[2*u+1][1]*a3;
        float s1 = acc[2*u][2]*a0 + acc[2*u][3]*a1 + acc[2*u+1][2]*a2 + acc[2*u+1][3]*a3;
        float d0 = acc[2*u][0]*b0 + acc[2*u][1]*b1 + acc[2*u+1][0]*b2 + acc[2*u+1][1]*b3;
        float d1 = acc[2*u][2]*b0 + acc[2*u][3]*b1 + acc[2*u+1][2]*b2 + acc[2*u+1][3]*b3;
        s0 += __shfl_xor_sync(0xffffffffu, s0, 1);
        s0 += __shfl_xor_sync(0xffffffffu, s0, 2);
        s1 += __shfl_xor_sync(0xffffffffu, s1, 1);
        s1 += __shfl_xor_sync(0xffffffffu, s1, 2);
        d0 += __shfl_xor_sync(0xffffffffu, d0, 1);
        d0 += __shfl_xor_sync(0xffffffffu, d0, 2);
        d1 += __shfl_xor_sync(0xffffffffu, d1, 1);
        d1 += __shfl_xor_sync(0xffffffffu, d1, 2);
        if ((lid & 3) == 0) {
            if (r0 < NN) { g_ss[r0 * 8 + hh] = s0; g_sd[r0 * 8 + hh] = d0; }
            if (r1 < NN) { g_ss[r1 * 8 + hh] = s1; g_sd[r1 * 8 + hh] = d1; }
        }
    }
}

// ---------------------------------------------------------------------------
// K3: edge pass A — compute exp(leaky_relu(logit)); spill fp16 numerators
// (coalesced 8B store), accumulate fp32 sums per (dst, head) via red.v4.
// 2 threads/edge (4 heads each).
// ---------------------------------------------------------------------------
__global__ void k_edgeA(const int* __restrict__ ei,
                        const float* __restrict__ ef,
                        const float* __restrict__ We) {
    int gid = blockIdx.x * 256 + threadIdx.x;   // grid exact: (EE*2) % 256 == 0
    int e = gid >> 1;
    int half = gid & 1;
    int src = ei[e];
    int dst = ei[EE + e];
    float f = __ldg(ef + e);
    float4 s = ((const float4*)g_ss)[src * 2 + half];
    float4 d = ((const float4*)g_sd)[dst * 2 + half];
    float4 w = ((const float4*)We)[half];
    float4 x;
    x.x = s.x + d.x + f * w.x;
    x.y = s.y + d.y + f * w.y;
    x.z = s.z + d.z + f * w.z;
    x.w = s.w + d.w + f * w.w;
    x.x = __expf(fmaxf(x.x, 0.2f * x.x));
    x.y = __expf(fmaxf(x.y, 0.2f * x.y));
    x.z = __expf(fmaxf(x.z, 0.2f * x.z));
    x.w = __expf(fmaxf(x.w, 0.2f * x.w));
    // fp16 spill (alpha gets fp16-rounded downstream anyway)
    __half2 p0 = __floats2half2_rn(x.x, x.y);
    __half2 p1 = __floats2half2_rn(x.z, x.w);
    *(uint2*)(g_exph + (size_t)e * 8 + half * 4) =
        make_uint2(*(unsigned*)&p0, *(unsigned*)&p1);
    red_add_v4(g_se + dst * 8 + half * 4, x);
}

// ---------------------------------------------------------------------------
// K4: edge pass B — alpha = 0.125 * exp16 (coalesced) / se (gather); fp16 row
// gather + HALF2 weighting/reduction; fp32 only at the final atomic.
// 8 lanes/edge; lane l loads chunks l and 8+l (head l>>1 / 4+(l>>1),
// feat-half l&1). xor-2 + xor-4 HADD2 reduction leaves lanes 0/1 holding
// feats 0-7 / 8-15 summed over all heads.
// ---------------------------------------------------------------------------
__global__ void k_edgeB(const int* __restrict__ ei,
                        float* __restrict__ out) {
    int gid = blockIdx.x * 256 + threadIdx.x;  // grid exact: (EE*8) % 256 == 0
    int e = gid >> 3;
    int l = gid & 7;
    int src = ei[e];
    int dst = ei[EE + e];

    // independent gathers issued early
    float expv = __half2float(g_exph[(size_t)e * 8 + l]);  // coalesced 2B/lane
    float sev = g_se[dst * 8 + l];                         // gathered sum
    const uint4* hv = (const uint4*)(g_hth + (size_t)src * 128);
    uint4 ua = hv[l];        // head l>>1,      feat-half l&1
    uint4 ub = hv[8 + l];    // head 4+(l>>1),  feat-half l&1

    float alpha = 0.125f * expv / sev;   // this lane = head l

    float a0 = __shfl_sync(0xffffffffu, alpha, (l >> 1), 8);
    float a1 = __shfl_sync(0xffffffffu, alpha, 4 + (l >> 1), 8);
    __half2 a0h = __float2half2_rn(a0);
    __half2 a1h = __float2half2_rn(a1);

    const __half2* uah = (const __half2*)&ua;
    const __half2* ubh = (const __half2*)&ub;
    unsigned acc[4];
#pragma unroll
    for (int i = 0; i < 4; i++) {
        __half2 t = __hfma2(uah[i], a0h, __hmul2(ubh[i], a1h));
        acc[i] = *(unsigned*)&t;
    }
    // head reduction (parity == feat-half preserved)
#pragma unroll
    for (int i = 0; i < 4; i++) {
        unsigned o = __shfl_xor_sync(0xffffffffu, acc[i], 2, 8);
        __half2 t = __hadd2(*(__half2*)&acc[i], *(__half2*)&o);
        acc[i] = *(unsigned*)&t;
    }
#pragma unroll
    for (int i = 0; i < 4; i++) {
        unsigned o = __shfl_xor_sync(0xffffffffu, acc[i], 4, 8);
        __half2 t = __hadd2(*(__half2*)&acc[i], *(__half2*)&o);
        acc[i] = *(unsigned*)&t;
    }

    if (l < 2) {
        float2 f0 = __half22float2(*(__half2*)&acc[0]);
        float2 f1 = __half22float2(*(__half2*)&acc[1]);
        float2 f2 = __half22float2(*(__half2*)&acc[2]);
        float2 f3 = __half22float2(*(__half2*)&acc[3]);
        float* base = out + (size_t)dst * 16 + l * 8;
        red_add_v4(base,     make_float4(f0.x, f0.y, f1.x, f1.y));
        red_add_v4(base + 4, make_float4(f2.x, f2.y, f3.x, f3.y));
    }
}

// ---------------------------------------------------------------------------
extern "C" void kernel_launch(void* const* d_in, const int* in_sizes, int n_in,
                              void* d_out, int out_size) {
    const float* h    = (const float*)d_in[0];
    const int*   ei   = (const int*)d_in[1];
    const float* ef   = (const float*)d_in[2];
    const float* Wn   = (const float*)d_in[3];
    const float* We   = (const float*)d_in[4];
    const float* asrc = (const float*)d_in[5];
    const float* adst = (const float*)d_in[6];
    float* out = (float*)d_out;

    cudaFuncSetAttribute(k_gemm, cudaFuncAttributeMaxDynamicSharedMemorySize, SM_TOT);

    k_prep<<<200, 256>>>(Wn, out);
    k_gemm<<<(NN + 63) / 64, 256, SM_TOT>>>(h, asrc, adst);
    k_edgeA<<<(EE * 2) / 256, 256>>>(ei, ef, We);
    k_edgeB<<<(EE * 8) / 256, 256>>>(ei, out);
}